// round 2
// baseline (speedup 1.0000x reference)
#include <cuda_runtime.h>
#include <math.h>

// Ping-pong scratch for Q1 = sigmoid(q-logit), shape [B,S,S] (B=4, S=160 -> 102400)
#define MAXQ 102400
__device__ float g_q1[2][MAXQ];

// MODE 0: first iteration, Q1 == 0.5 (no Q1 reads), writes Q1 -> g_q1[parity^1]
// MODE 1: middle iteration, reads g_q1[parity], writes g_q1[parity^1]
// MODE 2: final iteration, reads g_q1[parity], writes output probabilities
template<int MODE>
__global__ void __launch_bounds__(256)
mfvi_kernel(const float* __restrict__ se,
            const float* __restrict__ ss,
            const float* __restrict__ sc,
            const float* __restrict__ sg,
            const int* __restrict__ mask,      // bool materialized as int32
            float* __restrict__ out,
            int S, int parity)
{
    const int HT = 8;                       // h-values per block (== warps per block)
    int ntile = (S + HT - 1) / HT;
    int blk = blockIdx.x;
    int htile = blk % ntile;
    int m     = (blk / ntile) % S;
    int b     = blk / (ntile * S);
    int warp = threadIdx.x >> 5;
    int lane = threadIdx.x & 31;
    int h = htile * HT + warp;

    extern __shared__ float smbuf[];
    float* sm_row = smbuf;        // Q1[b, m, t]   (contiguous row)
    float* sm_col = smbuf + S;    // Q1[b, t, m]   (strided column)

    const float* __restrict__ q1_in = g_q1[parity & 1];

    if (MODE != 0) {
        for (int t = threadIdx.x; t < S; t += blockDim.x) {
            sm_row[t] = q1_in[(b * S + m) * S + t];
            sm_col[t] = q1_in[(b * S + t) * S + m];
        }
        __syncthreads();
    }

    if (h >= S) return;

    const long base = (((long)(b * S + m)) * S + h) * S;
    const int* __restrict__ mcol = mask + (long)b * S * S + h;  // mask[b,t,h], stride S

    float acc = 0.f;
    #pragma unroll 5
    for (int t = lane; t < S; t += 32) {
        bool ok = (mcol[(long)t * S] != 0) && (t != h) && (t != m);
        float vss = ss[base + t];
        float vsc = sc[base + t];
        float vsg = sg[base + t];
        float c;
        if (MODE == 0) {
            c = 0.5f * (vss + vsc + vsg);
        } else {
            float qa = q1_in[(b * S + t) * S + h];
            c = vss * qa + vsc * sm_row[t] + vsg * sm_col[t];
        }
        acc += ok ? c : 0.f;
    }

    // warp reduction over t
    #pragma unroll
    for (int off = 16; off; off >>= 1)
        acc += __shfl_down_sync(0xffffffffu, acc, off);

    if (lane == 0) {
        int idx = (b * S + m) * S + h;
        float f = (mask[idx] != 0) ? acc : 0.f;   // mask[b,m,h] gates the whole sum
        float q = se[idx] + f;
        if (MODE == 2) {
            // exp(log_softmax([0, q])) = [sigmoid(-q), sigmoid(q)]
            float p1 = 1.f / (1.f + expf(-q));
            float p0 = 1.f / (1.f + expf(q));
            out[(long)idx * 2 + 0] = p0;
            out[(long)idx * 2 + 1] = p1;
        } else {
            g_q1[(parity ^ 1) & 1][idx] = 1.f / (1.f + expf(-q));
        }
    }
}

extern "C" void kernel_launch(void* const* d_in, const int* in_sizes, int n_in,
                              void* d_out, int out_size)
{
    const float* se = (const float*)d_in[0];
    const float* ss = (const float*)d_in[1];
    const float* sc = (const float*)d_in[2];
    const float* sg = (const float*)d_in[3];
    const int* mask = (const int*)d_in[4];
    float* out = (float*)d_out;

    int BSS = in_sizes[0];                  // B*S*S
    int S = in_sizes[1] / BSS;              // (B*S^3)/(B*S^2)
    int B = BSS / (S * S);

    int ntile = (S + 7) / 8;
    dim3 grid(B * S * ntile);
    dim3 blockDim3(256);
    size_t smem = 2 * (size_t)S * sizeof(float);

    // iter 1: Q1=0.5, write g_q1[0]   (parity=1 -> out buffer = parity^1 = 0)
    mfvi_kernel<0><<<grid, blockDim3, smem>>>(se, ss, sc, sg, mask, out, S, 1);
    // iter 2: read g_q1[0], write g_q1[1]
    mfvi_kernel<1><<<grid, blockDim3, smem>>>(se, ss, sc, sg, mask, out, S, 0);
    // iter 3: read g_q1[1], write output
    mfvi_kernel<2><<<grid, blockDim3, smem>>>(se, ss, sc, sg, mask, out, S, 1);
}

// round 3
// speedup vs baseline: 1.5398x; 1.5398x over previous
#include <cuda_runtime.h>
#include <math.h>

// Scratch: Q1 ping-pong in both layouts + transposed mask. [B,S,S], B=4,S=160 -> 102400
#define MAXQ 102400
__device__ float g_q1 [2][MAXQ];   // Q1[b,m,h]   (row layout)
__device__ float g_q1T[2][MAXQ];   // Q1[b,h,m]   (transposed)
__device__ float g_mt [MAXQ];      // m_t[b,h,t] = (mask[b,t,h] && t!=h) ? 1 : 0

// Pre-pass: transpose mask into [b,h,t] float layout with t!=h folded in.
__global__ void mask_transpose_kernel(const int* __restrict__ mask, int S)
{
    int t = threadIdx.x;
    int h = blockIdx.x % S;
    int b = blockIdx.x / S;
    if (t < S) {
        int v = mask[(b * S + t) * S + h];
        g_mt[(b * S + h) * S + t] = (v != 0 && t != h) ? 1.f : 0.f;
    }
}

// MODE 0: first iteration, Q1 == 0.5 (no Q1 reads), writes q1/q1T buf (parity^1)
// MODE 1: middle iteration, reads buf parity, writes buf parity^1
// MODE 2: final iteration, reads buf parity, writes output probabilities
template<int MODE>
__global__ void __launch_bounds__(256)
mfvi_kernel(const float* __restrict__ se,
            const float* __restrict__ ss,
            const float* __restrict__ sc,
            const float* __restrict__ sg,
            const int* __restrict__ mask,
            float* __restrict__ out,
            int S, int parity)
{
    const int HT = 8;                       // h per block == warps per block
    int ntile = (S + HT - 1) / HT;
    int blk = blockIdx.x;
    int htile = blk % ntile;
    int m     = (blk / ntile) % S;
    int b     = blk / (ntile * S);
    int warp = threadIdx.x >> 5;
    int lane = threadIdx.x & 31;
    int h = htile * HT + warp;

    extern __shared__ float smbuf[];
    float* sm_row = smbuf;        // Q1[b,m,t]  = q1 [(b,m),t]  contiguous
    float* sm_col = smbuf + S;    // Q1[b,t,m]  = q1T[(b,m),t]  contiguous

    const float* __restrict__ q1_in  = g_q1 [parity & 1];
    const float* __restrict__ q1T_in = g_q1T[parity & 1];

    if (MODE != 0) {
        int nv = S >> 2;  // float4 count per row (S=160 -> 40)
        const float4* r4 = (const float4*)(q1_in  + (b * S + m) * S);
        const float4* c4 = (const float4*)(q1T_in + (b * S + m) * S);
        for (int i = threadIdx.x; i < 2 * nv; i += blockDim.x) {
            if (i < nv) ((float4*)sm_row)[i] = r4[i];
            else        ((float4*)sm_col)[i - nv] = c4[i - nv];
        }
        __syncthreads();
    }

    if (h >= S) return;

    const long base  = (((long)(b * S + m)) * S + h) * S;   // scores [b,m,h,t]
    const long baseh = ((long)(b * S + h)) * S;             // m_t / q1T rows over t

    float acc = 0.f;
    // Vectorized: each lane takes 4 consecutive t, warp stride 128 t
    for (int t4 = lane * 4; t4 + 3 < S; t4 += 128) {
        float4 vss = *(const float4*)(ss + base + t4);
        float4 vsc = *(const float4*)(sc + base + t4);
        float4 vsg = *(const float4*)(sg + base + t4);
        float4 vmt = *(const float4*)(g_mt + baseh + t4);
        float4 row = *(const float4*)(sm_row + t4);
        float4 col = *(const float4*)(sm_col + t4);
        float4 qa;
        if (MODE != 0) qa = *(const float4*)(q1T_in + baseh + t4);

        #pragma unroll
        for (int j = 0; j < 4; j++) {
            float mj = ((&vmt.x)[j]) * ((t4 + j) != m ? 1.f : 0.f);
            float c;
            if (MODE == 0)
                c = 0.5f * ((&vss.x)[j] + (&vsc.x)[j] + (&vsg.x)[j]);
            else
                c = (&vss.x)[j] * (&qa.x)[j]
                  + (&vsc.x)[j] * (&row.x)[j]
                  + (&vsg.x)[j] * (&col.x)[j];
            acc += mj * c;
        }
    }
    // Scalar tail (only if S % 4 != 0; S=160 skips this)
    for (int t = (S & ~3) + lane; t < S; t += 32) {
        float mj = g_mt[baseh + t] * ((t != m) ? 1.f : 0.f);
        float c;
        if (MODE == 0)
            c = 0.5f * (ss[base + t] + sc[base + t] + sg[base + t]);
        else
            c = ss[base + t] * q1T_in[baseh + t]
              + sc[base + t] * sm_row[t]
              + sg[base + t] * sm_col[t];
        acc += mj * c;
    }

    #pragma unroll
    for (int off = 16; off; off >>= 1)
        acc += __shfl_down_sync(0xffffffffu, acc, off);

    if (lane == 0) {
        int idx = (b * S + m) * S + h;
        float f = (mask[idx] != 0) ? acc : 0.f;
        float q = se[idx] + f;
        if (MODE == 2) {
            float p1 = 1.f / (1.f + expf(-q));
            float p0 = 1.f / (1.f + expf(q));
            out[(long)idx * 2 + 0] = p0;
            out[(long)idx * 2 + 1] = p1;
        } else {
            float q1v = 1.f / (1.f + expf(-q));
            int ob = (parity ^ 1) & 1;
            g_q1 [ob][idx] = q1v;
            g_q1T[ob][(b * S + h) * S + m] = q1v;
        }
    }
}

extern "C" void kernel_launch(void* const* d_in, const int* in_sizes, int n_in,
                              void* d_out, int out_size)
{
    const float* se = (const float*)d_in[0];
    const float* ss = (const float*)d_in[1];
    const float* sc = (const float*)d_in[2];
    const float* sg = (const float*)d_in[3];
    const int* mask = (const int*)d_in[4];
    float* out = (float*)d_out;

    int BSS = in_sizes[0];                  // B*S*S
    int S = in_sizes[1] / BSS;              // (B*S^3)/(B*S^2)
    int B = BSS / (S * S);

    mask_transpose_kernel<<<B * S, (S + 31) & ~31>>>(mask, S);

    int ntile = (S + 7) / 8;
    dim3 grid(B * S * ntile);
    size_t smem = 2 * (size_t)S * sizeof(float);

    mfvi_kernel<0><<<grid, 256, smem>>>(se, ss, sc, sg, mask, out, S, 1);
    mfvi_kernel<1><<<grid, 256, smem>>>(se, ss, sc, sg, mask, out, S, 0);
    mfvi_kernel<2><<<grid, 256, smem>>>(se, ss, sc, sg, mask, out, S, 1);
}

// round 4
// speedup vs baseline: 2.4542x; 1.5939x over previous
#include <cuda_runtime.h>
#include <math.h>

// Scratch: Q1 ping-pong in both layouts + transposed mask. [B,S,S], B=4,S=160 -> 102400
#define MAXQ 102400
__device__ float g_q1 [2][MAXQ];   // Q1[b,m,h]   (row layout)
__device__ float g_q1T[2][MAXQ];   // Q1[b,h,m]   (transposed)
__device__ float g_mt [MAXQ];      // m_t[b,h,t] = (mask[b,t,h] && t!=h) ? 1 : 0

// Pre-pass: transpose mask into [b,h,t] float layout with t!=h folded in.
__global__ void mask_transpose_kernel(const int* __restrict__ mask, int S)
{
    int t = threadIdx.x;
    int h = blockIdx.x % S;
    int b = blockIdx.x / S;
    if (t < S) {
        int v = mask[(b * S + t) * S + h];
        g_mt[(b * S + h) * S + t] = (v != 0 && t != h) ? 1.f : 0.f;
    }
}

// MODE 0: iter 1, Q1 == 0.5 (no Q1 reads). MODE 1: middle iter. MODE 2: final -> output.
template<int MODE>
__global__ void __launch_bounds__(256)
mfvi_kernel(const float* __restrict__ se,
            const float* __restrict__ ss,
            const float* __restrict__ sc,
            const float* __restrict__ sg,
            const int* __restrict__ mask,
            float* __restrict__ out,
            int S, int parity)
{
    const int RW = 4;                      // h-rows per warp
    const int HT = 8 * RW;                 // h per block (8 warps)
    int ntile = (S + HT - 1) / HT;
    int blk = blockIdx.x;
    int htile = blk % ntile;
    int m     = (blk / ntile) % S;
    int b     = blk / (ntile * S);
    int warp = threadIdx.x >> 5;
    int lane = threadIdx.x & 31;
    int h0 = htile * HT + warp * RW;

    extern __shared__ float smbuf[];
    float* sm_row = smbuf;        // Q1[b,m,t]  = q1 [(b,m),t]  contiguous
    float* sm_col = smbuf + S;    // Q1[b,t,m]  = q1T[(b,m),t]  contiguous

    const float* __restrict__ q1_in  = g_q1 [parity & 1];
    const float* __restrict__ q1T_in = g_q1T[parity & 1];

    if (MODE != 0) {
        int nv = S >> 2;
        const float4* r4 = (const float4*)(q1_in  + (b * S + m) * S);
        const float4* c4 = (const float4*)(q1T_in + (b * S + m) * S);
        for (int i = threadIdx.x; i < 2 * nv; i += blockDim.x) {
            if (i < nv) ((float4*)sm_row)[i] = r4[i];
            else        ((float4*)sm_col)[i - nv] = c4[i - nv];
        }
        __syncthreads();
    }

    if (h0 >= S) return;
    int nrow = (S - h0 < RW) ? (S - h0) : RW;

    const long base  = (((long)(b * S + m)) * S + h0) * S;  // scores, flat over rows*t
    const long baseh = ((long)(b * S + h0)) * S;            // m_t / q1T, flat over rows*t

    int FV = S >> 2;            // float4 per row (40 for S=160)
    int F  = nrow * FV;         // flat float4 count (160 for full warp)

    float acc0 = 0.f, acc1 = 0.f, acc2 = 0.f, acc3 = 0.f;
    #pragma unroll 5
    for (int f = lane; f < F; f += 32) {
        int row = f / FV;
        int t4  = (f - row * FV) << 2;
        long off = (long)f << 2;           // == row*S + t4
        float4 vss = *(const float4*)(ss + base + off);
        float4 vsc = *(const float4*)(sc + base + off);
        float4 vsg = *(const float4*)(sg + base + off);
        float4 vmt = *(const float4*)(g_mt + baseh + off);
        float4 qa, qrow, qcol;
        if (MODE != 0) {
            qa   = *(const float4*)(q1T_in + baseh + off);
            qrow = *(const float4*)(sm_row + t4);
            qcol = *(const float4*)(sm_col + t4);
        }

        float c = 0.f;
        #pragma unroll
        for (int j = 0; j < 4; j++) {
            float mj = ((&vmt.x)[j]) * ((t4 + j) != m ? 1.f : 0.f);
            if (MODE == 0)
                c += mj * 0.5f * ((&vss.x)[j] + (&vsc.x)[j] + (&vsg.x)[j]);
            else
                c += mj * ((&vss.x)[j] * (&qa.x)[j]
                         + (&vsc.x)[j] * (&qrow.x)[j]
                         + (&vsg.x)[j] * (&qcol.x)[j]);
        }
        acc0 += (row == 0) ? c : 0.f;
        acc1 += (row == 1) ? c : 0.f;
        acc2 += (row == 2) ? c : 0.f;
        acc3 += (row == 3) ? c : 0.f;
    }

    // warp reductions (4 rows)
    #pragma unroll
    for (int off = 16; off; off >>= 1) {
        acc0 += __shfl_down_sync(0xffffffffu, acc0, off);
        acc1 += __shfl_down_sync(0xffffffffu, acc1, off);
        acc2 += __shfl_down_sync(0xffffffffu, acc2, off);
        acc3 += __shfl_down_sync(0xffffffffu, acc3, off);
    }

    if (lane == 0) {
        float accs[RW] = {acc0, acc1, acc2, acc3};
        #pragma unroll
        for (int r = 0; r < RW; r++) {
            if (r >= nrow) break;
            int h = h0 + r;
            int idx = (b * S + m) * S + h;
            float f = (mask[idx] != 0) ? accs[r] : 0.f;
            float q = se[idx] + f;
            if (MODE == 2) {
                out[(long)idx * 2 + 0] = 1.f / (1.f + expf(q));
                out[(long)idx * 2 + 1] = 1.f / (1.f + expf(-q));
            } else {
                float q1v = 1.f / (1.f + expf(-q));
                int ob = (parity ^ 1) & 1;
                g_q1 [ob][idx] = q1v;
                g_q1T[ob][(b * S + h) * S + m] = q1v;
            }
        }
    }
}

extern "C" void kernel_launch(void* const* d_in, const int* in_sizes, int n_in,
                              void* d_out, int out_size)
{
    const float* se = (const float*)d_in[0];
    const float* ss = (const float*)d_in[1];
    const float* sc = (const float*)d_in[2];
    const float* sg = (const float*)d_in[3];
    const int* mask = (const int*)d_in[4];
    float* out = (float*)d_out;

    int BSS = in_sizes[0];                  // B*S*S
    int S = in_sizes[1] / BSS;              // (B*S^3)/(B*S^2)
    int B = BSS / (S * S);

    mask_transpose_kernel<<<B * S, (S + 31) & ~31>>>(mask, S);

    int ntile = (S + 31) / 32;              // 32 h per block
    dim3 grid(B * S * ntile);
    size_t smem = 2 * (size_t)S * sizeof(float);

    mfvi_kernel<0><<<grid, 256, smem>>>(se, ss, sc, sg, mask, out, S, 1);
    mfvi_kernel<1><<<grid, 256, smem>>>(se, ss, sc, sg, mask, out, S, 0);
    mfvi_kernel<2><<<grid, 256, smem>>>(se, ss, sc, sg, mask, out, S, 1);
}

// round 5
// speedup vs baseline: 2.6898x; 1.0960x over previous
#include <cuda_runtime.h>
#include <math.h>

// Scratch: Q1 ping-pong in both layouts + transposed mask. [B,S,S], B=4,S=160 -> 102400
#define MAXQ 102400
__device__ float g_q1 [2][MAXQ];   // Q1[b,m,h]   (row layout)
__device__ float g_q1T[2][MAXQ];   // Q1[b,h,m]   (transposed)
__device__ float g_mt [MAXQ];      // m_t[b,h,t] = (mask[b,t,h] && t!=h) ? 1 : 0

// Pre-pass: transpose mask into [b,h,t] float layout with t!=h folded in.
__global__ void mask_transpose_kernel(const int* __restrict__ mask, int S)
{
    int t = threadIdx.x;
    int h = blockIdx.x % S;
    int b = blockIdx.x / S;
    if (t < S) {
        int v = mask[(b * S + t) * S + h];
        g_mt[(b * S + h) * S + t] = (v != 0 && t != h) ? 1.f : 0.f;
    }
}

// MODE 0: iter 1, Q1 == 0.5 (no Q1 reads). MODE 1: middle iter. MODE 2: final -> output.
template<int MODE>
__global__ void __launch_bounds__(256)
mfvi_kernel(const float* __restrict__ se,
            const float* __restrict__ ss,
            const float* __restrict__ sc,
            const float* __restrict__ sg,
            const int* __restrict__ mask,
            float* __restrict__ out,
            int S, int parity)
{
    const int RW = 4;                      // h-rows per warp (one per 8-lane group)
    const int HT = 8 * RW;                 // h per block (8 warps)
    int ntile = (S + HT - 1) / HT;
    int blk = blockIdx.x;
    int htile = blk % ntile;
    int m     = (blk / ntile) % S;
    int b     = blk / (ntile * S);
    int warp = threadIdx.x >> 5;
    int lane = threadIdx.x & 31;
    int g    = lane >> 3;                  // group (row) index 0..3
    int li   = lane & 7;                   // lane within group
    int h    = htile * HT + warp * RW + g; // this thread's h-row

    extern __shared__ float smbuf[];
    float* sm_row = smbuf;        // Q1[b,m,t]  = q1 [(b,m),t]  contiguous
    float* sm_col = smbuf + S;    // Q1[b,t,m]  = q1T[(b,m),t]  contiguous

    const float* __restrict__ q1_in  = g_q1 [parity & 1];
    const float* __restrict__ q1T_in = g_q1T[parity & 1];

    if (MODE != 0) {
        int nv = S >> 2;
        const float4* r4 = (const float4*)(q1_in  + (b * S + m) * S);
        const float4* c4 = (const float4*)(q1T_in + (b * S + m) * S);
        for (int i = threadIdx.x; i < 2 * nv; i += blockDim.x) {
            if (i < nv) ((float4*)sm_row)[i] = r4[i];
            else        ((float4*)sm_col)[i - nv] = c4[i - nv];
        }
        __syncthreads();
    }

    bool valid = (h < S);
    int FV = S >> 2;                       // float4 per row (40 for S=160)

    const float4* p_ss = (const float4*)(ss + ((((long)(b * S + m)) * S + h) * S));
    const float4* p_sc = (const float4*)(sc + ((((long)(b * S + m)) * S + h) * S));
    const float4* p_sg = (const float4*)(sg + ((((long)(b * S + m)) * S + h) * S));
    const float4* p_mt = (const float4*)(g_mt + ((long)(b * S + h)) * S);
    const float4* p_qa = (const float4*)(q1T_in + ((long)(b * S + h)) * S);

    float acc = 0.f;
    if (valid) {
        #pragma unroll 5
        for (int v = li; v < FV; v += 8) {
            float4 vss = p_ss[v];
            float4 vsc = p_sc[v];
            float4 vsg = p_sg[v];
            float4 vmt = p_mt[v];
            int t4 = v << 2;
            float4 qa, qrow, qcol;
            if (MODE != 0) {
                qa   = p_qa[v];
                qrow = ((const float4*)sm_row)[v];
                qcol = ((const float4*)sm_col)[v];
            }
            #pragma unroll
            for (int j = 0; j < 4; j++) {
                float mj = ((&vmt.x)[j]) * ((t4 + j) != m ? 1.f : 0.f);
                if (MODE == 0)
                    acc += mj * 0.5f * ((&vss.x)[j] + (&vsc.x)[j] + (&vsg.x)[j]);
                else
                    acc += mj * ((&vss.x)[j] * (&qa.x)[j]
                               + (&vsc.x)[j] * (&qrow.x)[j]
                               + (&vsg.x)[j] * (&qcol.x)[j]);
            }
        }
    }

    // reduce within the 8-lane group
    acc += __shfl_down_sync(0xffffffffu, acc, 4, 8);
    acc += __shfl_down_sync(0xffffffffu, acc, 2, 8);
    acc += __shfl_down_sync(0xffffffffu, acc, 1, 8);

    if (li == 0 && valid) {
        int idx = (b * S + m) * S + h;
        float f = (mask[idx] != 0) ? acc : 0.f;
        float q = se[idx] + f;
        if (MODE == 2) {
            out[(long)idx * 2 + 0] = 1.f / (1.f + expf(q));
            out[(long)idx * 2 + 1] = 1.f / (1.f + expf(-q));
        } else {
            float q1v = 1.f / (1.f + expf(-q));
            int ob = (parity ^ 1) & 1;
            g_q1 [ob][idx] = q1v;
            g_q1T[ob][(b * S + h) * S + m] = q1v;
        }
    }
}

extern "C" void kernel_launch(void* const* d_in, const int* in_sizes, int n_in,
                              void* d_out, int out_size)
{
    const float* se = (const float*)d_in[0];
    const float* ss = (const float*)d_in[1];
    const float* sc = (const float*)d_in[2];
    const float* sg = (const float*)d_in[3];
    const int* mask = (const int*)d_in[4];
    float* out = (float*)d_out;

    int BSS = in_sizes[0];                  // B*S*S
    int S = in_sizes[1] / BSS;              // (B*S^3)/(B*S^2)
    int B = BSS / (S * S);

    mask_transpose_kernel<<<B * S, (S + 31) & ~31>>>(mask, S);

    int ntile = (S + 31) / 32;              // 32 h per block
    dim3 grid(B * S * ntile);
    size_t smem = 2 * (size_t)S * sizeof(float);

    mfvi_kernel<0><<<grid, 256, smem>>>(se, ss, sc, sg, mask, out, S, 1);
    mfvi_kernel<1><<<grid, 256, smem>>>(se, ss, sc, sg, mask, out, S, 0);
    mfvi_kernel<2><<<grid, 256, smem>>>(se, ss, sc, sg, mask, out, S, 1);
}